// round 1
// baseline (speedup 1.0000x reference)
#include <cuda_runtime.h>
#include <cuda_bf16.h>
#include <math.h>

// Problem constants
#define Bc 2
#define Tc 2048
#define Dc 1024
#define Hc 16
#define Lc 8
#define Ic 4096
#define HD 64           // head dim
#define ROWS (Bc*Tc)    // 4096 token rows
#define LN_EPS 1e-5f
#define MASK_BIAS -10000.0f

// ---------------- scratch (static device globals; no allocation) -------------
__device__ float g_h[ROWS * Dc];        // residual stream
__device__ float g_x[ROWS * Dc];        // layernorm output
__device__ float g_qkv[ROWS * 3 * Dc];  // qkv projection
__device__ float g_ctx[ROWS * Dc];      // attention context
__device__ float g_act[ROWS * Ic];      // ffn inner activation

// ---------------- utility ----------------------------------------------------
__inline__ __device__ float warp_sum(float v) {
    #pragma unroll
    for (int o = 16; o > 0; o >>= 1) v += __shfl_xor_sync(0xffffffffu, v, o);
    return v;
}

// ---------------- copy -------------------------------------------------------
__global__ void copy_kernel(const float* __restrict__ src, float* __restrict__ dst, int n) {
    int i = blockIdx.x * blockDim.x + threadIdx.x;
    if (i < n) dst[i] = src[i];
}

// ---------------- layernorm --------------------------------------------------
// one block per row of D=1024
__global__ __launch_bounds__(256) void ln_kernel(
    const float* __restrict__ in, const float* __restrict__ w,
    const float* __restrict__ b, float* __restrict__ out)
{
    int row = blockIdx.x;
    const float* x = in + (size_t)row * Dc;
    float s = 0.f, s2 = 0.f;
    for (int i = threadIdx.x; i < Dc; i += 256) {
        float v = x[i];
        s += v; s2 += v * v;
    }
    __shared__ float r1[8], r2[8];
    s = warp_sum(s); s2 = warp_sum(s2);
    int wid = threadIdx.x >> 5, lane = threadIdx.x & 31;
    if (lane == 0) { r1[wid] = s; r2[wid] = s2; }
    __syncthreads();
    if (wid == 0) {
        s  = (lane < 8) ? r1[lane] : 0.f;
        s2 = (lane < 8) ? r2[lane] : 0.f;
        s = warp_sum(s); s2 = warp_sum(s2);
        if (lane == 0) { r1[0] = s; r2[0] = s2; }
    }
    __syncthreads();
    float mean = r1[0] * (1.0f / Dc);
    float var  = r2[0] * (1.0f / Dc) - mean * mean;
    float inv  = rsqrtf(var + LN_EPS);
    float* o = out + (size_t)row * Dc;
    for (int i = threadIdx.x; i < Dc; i += 256)
        o[i] = (x[i] - mean) * inv * w[i] + b[i];
}

// ---------------- GEMM: C = act(A[M,K] @ W[K,N] + bias) (+ residual) ---------
#define BM 64
#define BN 64
#define BKG 16
template<bool RELU, bool RES>
__global__ __launch_bounds__(256) void gemm_kernel(
    const float* __restrict__ A, const float* __restrict__ W,
    const float* __restrict__ bias, const float* __restrict__ res,
    float* __restrict__ C, int M, int N, int K)
{
    __shared__ __align__(16) float As[BKG][BM];   // transposed A tile
    __shared__ __align__(16) float Bs[BKG][BN];
    int tid = threadIdx.x;
    int bm = blockIdx.y * BM;
    int bn = blockIdx.x * BN;
    int tr = tid >> 4;          // 0..15
    int tc = tid & 15;          // 0..15
    // A load: row a_r (0..63), 4 cols at a_c
    int a_r = tid >> 2, a_c = (tid & 3) << 2;
    // B load: row b_r (0..15), 4 cols at b_c
    int b_r = tid >> 4, b_c = (tid & 15) << 2;

    float acc[4][4] = {};
    const float* Aptr = A + (size_t)(bm + a_r) * K + a_c;
    const float* Wptr = W + (size_t)b_r * N + bn + b_c;

    for (int k0 = 0; k0 < K; k0 += BKG) {
        float4 av = *(const float4*)(Aptr + k0);
        As[a_c + 0][a_r] = av.x;
        As[a_c + 1][a_r] = av.y;
        As[a_c + 2][a_r] = av.z;
        As[a_c + 3][a_r] = av.w;
        float4 bv = *(const float4*)(Wptr + (size_t)k0 * N);
        *(float4*)&Bs[b_r][b_c] = bv;
        __syncthreads();
        #pragma unroll
        for (int kk = 0; kk < BKG; kk++) {
            float4 a4 = *(const float4*)&As[kk][tr << 2];
            float4 b4 = *(const float4*)&Bs[kk][tc << 2];
            float a[4] = {a4.x, a4.y, a4.z, a4.w};
            float bb[4] = {b4.x, b4.y, b4.z, b4.w};
            #pragma unroll
            for (int i = 0; i < 4; i++)
                #pragma unroll
                for (int j = 0; j < 4; j++)
                    acc[i][j] += a[i] * bb[j];
        }
        __syncthreads();
    }
    #pragma unroll
    for (int i = 0; i < 4; i++) {
        int row = bm + (tr << 2) + i;
        #pragma unroll
        for (int j = 0; j < 4; j++) {
            int col = bn + (tc << 2) + j;
            float v = acc[i][j] + bias[col];
            if (RELU) v = fmaxf(v, 0.0f);
            size_t idx = (size_t)row * N + col;
            if (RES) v += res[idx];
            C[idx] = v;
        }
    }
}

// ---------------- fused causal attention (flash-lite) ------------------------
// grid: (T/BQ, B*H), 256 threads. qkv layout: [B, T, 3*D], heads are 64-wide slices.
#define BQ 32
#define BKT 32
__global__ __launch_bounds__(256) void attn_kernel(
    const float* __restrict__ qkv, const float* __restrict__ amask,
    float* __restrict__ ctx)
{
    __shared__ __align__(16) float Qs[BQ][HD];
    __shared__ __align__(16) float Ks[BKT][HD];
    __shared__ __align__(16) float Vs[BKT][HD];
    __shared__ float Ss[BQ][BKT];
    __shared__ float mrow[BQ], lrow[BQ], crow[BQ];

    int tid = threadIdx.x;
    int bh = blockIdx.y;
    int b = bh / Hc, hh = bh % Hc;
    int q0 = blockIdx.x * BQ;

    const float* qbase = qkv + (size_t)b * Tc * 3 * Dc + hh * HD;
    const float* kbase = qbase + Dc;
    const float* vbase = qbase + 2 * Dc;

    // load Q tile
    for (int i = tid; i < BQ * HD; i += 256) {
        int r = i >> 6, d = i & 63;
        Qs[r][d] = qbase[(size_t)(q0 + r) * 3 * Dc + d];
    }
    if (tid < BQ) { mrow[tid] = -1e30f; lrow[tid] = 0.f; }

    int tq = tid >> 3;           // 0..31 (q row for accumulation)
    int dbase = (tid & 7) << 3;  // 0..56 (8-wide d slice)
    float acc[8] = {};
    const float scale = 0.125f;  // 1/sqrt(64)

    int ntiles = blockIdx.x + 1;
    for (int kt = 0; kt < ntiles; kt++) {
        int kk0 = kt * BKT;
        __syncthreads();  // protect Ks/Vs/Ss from previous iteration readers
        for (int i = tid; i < BKT * HD; i += 256) {
            int r = i >> 6, d = i & 63;
            Ks[r][d] = kbase[(size_t)(kk0 + r) * 3 * Dc + d];
            Vs[r][d] = vbase[(size_t)(kk0 + r) * 3 * Dc + d];
        }
        __syncthreads();
        // scores: thread computes row sq = tid/8, 4 cols at (tid%8)*4
        {
            int sq = tid >> 3;
            int c0 = (tid & 7) << 2;
            float sv[4] = {0.f, 0.f, 0.f, 0.f};
            #pragma unroll
            for (int d = 0; d < HD; d++) {
                float qv = Qs[sq][d];
                sv[0] += qv * Ks[c0 + 0][d];
                sv[1] += qv * Ks[c0 + 1][d];
                sv[2] += qv * Ks[c0 + 2][d];
                sv[3] += qv * Ks[c0 + 3][d];
            }
            int qg = q0 + sq;
            #pragma unroll
            for (int j = 0; j < 4; j++) {
                int kg = kk0 + c0 + j;
                float s;
                if (kg <= qg)
                    s = sv[j] * scale + (1.0f - amask[b * Tc + kg]) * MASK_BIAS;
                else
                    s = -1e30f;  // exp underflows to exactly 0, same as ref
                Ss[sq][c0 + j] = s;
            }
        }
        __syncthreads();
        // online softmax update (one thread per q row)
        if (tid < BQ) {
            float m = mrow[tid];
            float tm = m;
            #pragma unroll
            for (int j = 0; j < BKT; j++) tm = fmaxf(tm, Ss[tid][j]);
            float corr = __expf(m - tm);
            float l = lrow[tid] * corr;
            #pragma unroll
            for (int j = 0; j < BKT; j++) {
                float p = __expf(Ss[tid][j] - tm);
                Ss[tid][j] = p;
                l += p;
            }
            mrow[tid] = tm; lrow[tid] = l; crow[tid] = corr;
        }
        __syncthreads();
        // accumulate P @ V
        float corr = crow[tq];
        #pragma unroll
        for (int j = 0; j < 8; j++) acc[j] *= corr;
        #pragma unroll 4
        for (int kkk = 0; kkk < BKT; kkk++) {
            float p = Ss[tq][kkk];
            float4 v0 = *(const float4*)&Vs[kkk][dbase];
            float4 v1 = *(const float4*)&Vs[kkk][dbase + 4];
            acc[0] += p * v0.x; acc[1] += p * v0.y;
            acc[2] += p * v0.z; acc[3] += p * v0.w;
            acc[4] += p * v1.x; acc[5] += p * v1.y;
            acc[6] += p * v1.z; acc[7] += p * v1.w;
        }
    }
    __syncthreads();
    float linv = 1.0f / lrow[tq];
    size_t obase = ((size_t)(b * Tc + q0 + tq)) * Dc + hh * HD + dbase;
    #pragma unroll
    for (int j = 0; j < 8; j++) ctx[obase + j] = acc[j] * linv;
}

// ---------------- launch -----------------------------------------------------
extern "C" void kernel_launch(void* const* d_in, const int* in_sizes, int n_in,
                              void* d_out, int out_size)
{
    const float* emb    = (const float*)d_in[0];
    const float* amask  = (const float*)d_in[1];
    const float* ln1_w  = (const float*)d_in[2];
    const float* ln1_b  = (const float*)d_in[3];
    const float* attn_w = (const float*)d_in[4];
    const float* attn_b = (const float*)d_in[5];
    const float* proj_w = (const float*)d_in[6];
    const float* proj_b = (const float*)d_in[7];
    const float* ln2_w  = (const float*)d_in[8];
    const float* ln2_b  = (const float*)d_in[9];
    const float* fc_w   = (const float*)d_in[10];
    const float* fc_b   = (const float*)d_in[11];
    const float* fcp_w  = (const float*)d_in[12];
    const float* fcp_b  = (const float*)d_in[13];
    const float* lnf_w  = (const float*)d_in[14];
    const float* lnf_b  = (const float*)d_in[15];
    float* out = (float*)d_out;

    float *h, *x, *qkvb, *ctx, *act;
    cudaGetSymbolAddress((void**)&h,    g_h);
    cudaGetSymbolAddress((void**)&x,    g_x);
    cudaGetSymbolAddress((void**)&qkvb, g_qkv);
    cudaGetSymbolAddress((void**)&ctx,  g_ctx);
    cudaGetSymbolAddress((void**)&act,  g_act);

    // h = inputs_embeds
    {
        int n = ROWS * Dc;
        copy_kernel<<<(n + 255) / 256, 256>>>(emb, h, n);
    }

    for (int l = 0; l < Lc; l++) {
        // x = ln1(h)
        ln_kernel<<<ROWS, 256>>>(h, ln1_w + (size_t)l * Dc, ln1_b + (size_t)l * Dc, x);
        // qkv = x @ attn_w + attn_b
        gemm_kernel<false, false><<<dim3(3 * Dc / BN, ROWS / BM), 256>>>(
            x, attn_w + (size_t)l * Dc * 3 * Dc, attn_b + (size_t)l * 3 * Dc,
            nullptr, qkvb, ROWS, 3 * Dc, Dc);
        // ctx = attention(qkv)
        attn_kernel<<<dim3(Tc / BQ, Bc * Hc), 256>>>(qkvb, amask, ctx);
        // h = h + ctx @ proj_w + proj_b
        gemm_kernel<false, true><<<dim3(Dc / BN, ROWS / BM), 256>>>(
            ctx, proj_w + (size_t)l * Dc * Dc, proj_b + (size_t)l * Dc,
            h, h, ROWS, Dc, Dc);
        // x = ln2(h)
        ln_kernel<<<ROWS, 256>>>(h, ln2_w + (size_t)l * Dc, ln2_b + (size_t)l * Dc, x);
        // act = relu(x @ fc_w + fc_b)
        gemm_kernel<true, false><<<dim3(Ic / BN, ROWS / BM), 256>>>(
            x, fc_w + (size_t)l * Dc * Ic, fc_b + (size_t)l * Ic,
            nullptr, act, ROWS, Ic, Dc);
        // h = h + act @ fcp_w + fcp_b
        gemm_kernel<false, true><<<dim3(Dc / BN, ROWS / BM), 256>>>(
            act, fcp_w + (size_t)l * Ic * Dc, fcp_b + (size_t)l * Dc,
            h, h, ROWS, Dc, Ic);
    }
    // out = ln_f(h)
    ln_kernel<<<ROWS, 256>>>(h, lnf_w, lnf_b, out);
}

// round 3
// speedup vs baseline: 1.2783x; 1.2783x over previous
#include <cuda_runtime.h>
#include <cuda_bf16.h>
#include <math.h>

// Problem constants
#define Bc 2
#define Tc 2048
#define Dc 1024
#define Hc 16
#define Lc 8
#define Ic 4096
#define HD 64
#define ROWS (Bc*Tc)    // 4096 token rows
#define LN_EPS 1e-5f
#define MASK_BIAS -10000.0f

typedef __nv_bfloat16 bf16;

// ---------------- scratch (static device globals; no allocation) -------------
__device__ float g_h[ROWS * Dc];            // residual stream (fp32)
__device__ float g_qkv[ROWS * 3 * Dc];      // qkv projection (fp32)
__device__ bf16  g_xhi[ROWS * Dc],  g_xlo[ROWS * Dc];     // LN output split
__device__ bf16  g_chi[ROWS * Dc],  g_clo[ROWS * Dc];     // attention ctx split
__device__ bf16  g_ahi[ROWS * Ic],  g_alo[ROWS * Ic];     // ffn inner split
// weight splits
__device__ bf16 g_wqkv_hi[Lc*Dc*3*Dc], g_wqkv_lo[Lc*Dc*3*Dc];
__device__ bf16 g_wprj_hi[Lc*Dc*Dc],   g_wprj_lo[Lc*Dc*Dc];
__device__ bf16 g_wfc_hi [Lc*Dc*Ic],   g_wfc_lo [Lc*Dc*Ic];
__device__ bf16 g_wfp_hi [Lc*Ic*Dc],   g_wfp_lo [Lc*Ic*Dc];

// ---------------- utility ----------------------------------------------------
__inline__ __device__ float warp_sum(float v) {
    #pragma unroll
    for (int o = 16; o > 0; o >>= 1) v += __shfl_xor_sync(0xffffffffu, v, o);
    return v;
}

__device__ __forceinline__ void split2(float v, bf16& hi, bf16& lo) {
    hi = __float2bfloat16(v);
    lo = __float2bfloat16(v - __bfloat162float(hi));
}

// ---------------- copy / weight split ----------------------------------------
__global__ void copy_kernel(const float* __restrict__ src, float* __restrict__ dst, int n) {
    int i = blockIdx.x * blockDim.x + threadIdx.x;
    if (i < n) dst[i] = src[i];
}

__global__ void split4_kernel(const float* __restrict__ src,
                              bf16* __restrict__ hi, bf16* __restrict__ lo, int n4) {
    int i = blockIdx.x * blockDim.x + threadIdx.x;
    if (i >= n4) return;
    float4 v = ((const float4*)src)[i];
    bf16 h0,l0,h1,l1,h2,l2,h3,l3;
    split2(v.x,h0,l0); split2(v.y,h1,l1); split2(v.z,h2,l2); split2(v.w,h3,l3);
    __nv_bfloat162* H = (__nv_bfloat162*)(hi + 4*(size_t)i);
    __nv_bfloat162* L = (__nv_bfloat162*)(lo + 4*(size_t)i);
    H[0] = __nv_bfloat162(h0,h1); H[1] = __nv_bfloat162(h2,h3);
    L[0] = __nv_bfloat162(l0,l1); L[1] = __nv_bfloat162(l2,l3);
}

// ---------------- layernorm (optionally writing hi/lo bf16 split) ------------
template<bool SPLIT>
__global__ __launch_bounds__(256) void ln_kernel(
    const float* __restrict__ in, const float* __restrict__ w,
    const float* __restrict__ b, float* __restrict__ outf,
    bf16* __restrict__ outhi, bf16* __restrict__ outlo)
{
    int row = blockIdx.x;
    const float* x = in + (size_t)row * Dc;
    float s = 0.f, s2 = 0.f;
    for (int i = threadIdx.x; i < Dc; i += 256) {
        float v = x[i]; s += v; s2 += v * v;
    }
    __shared__ float r1[8], r2[8];
    s = warp_sum(s); s2 = warp_sum(s2);
    int wid = threadIdx.x >> 5, lane = threadIdx.x & 31;
    if (lane == 0) { r1[wid] = s; r2[wid] = s2; }
    __syncthreads();
    if (wid == 0) {
        s  = (lane < 8) ? r1[lane] : 0.f;
        s2 = (lane < 8) ? r2[lane] : 0.f;
        s = warp_sum(s); s2 = warp_sum(s2);
        if (lane == 0) { r1[0] = s; r2[0] = s2; }
    }
    __syncthreads();
    float mean = r1[0] * (1.0f / Dc);
    float var  = r2[0] * (1.0f / Dc) - mean * mean;
    float inv  = rsqrtf(var + LN_EPS);
    for (int i = threadIdx.x; i < Dc; i += 256) {
        float v = (x[i] - mean) * inv * w[i] + b[i];
        if (SPLIT) {
            bf16 hh, ll; split2(v, hh, ll);
            outhi[(size_t)row * Dc + i] = hh;
            outlo[(size_t)row * Dc + i] = ll;
        } else {
            outf[(size_t)row * Dc + i] = v;
        }
    }
}

// ---------------- tensor-core GEMM (bf16x3 emulation of fp32) -----------------
// C[M,N] = A[M,K] @ W[K,N] + bias  computed as Ahi*Whi + Ahi*Wlo + Alo*Whi
// EPI 0: Cf = v ;  EPI 1: Cf = res + v ;  EPI 2: relu(v) -> (Chi, Clo) split
#define GBM 128
#define GBN 128
#define GBK 32
#define APAD 8
#define BPAD 8
#define ASTRIDE (GBK + APAD)     // 40
#define BSTRIDE (GBN + BPAD)     // 136
#define SA_ELEMS (2*2*GBM*ASTRIDE)           // 40960 bf16
#define SB_ELEMS (2*2*GBK*BSTRIDE)           // 17408 bf16
#define GSMEM_BYTES ((SA_ELEMS + SB_ELEMS) * 2)

__device__ __forceinline__ void ldsm4(unsigned* r, unsigned addr) {
    asm volatile("ldmatrix.sync.aligned.m8n8.x4.shared.b16 {%0,%1,%2,%3},[%4];"
        : "=r"(r[0]), "=r"(r[1]), "=r"(r[2]), "=r"(r[3]) : "r"(addr));
}
__device__ __forceinline__ void ldsm4t(unsigned* r, unsigned addr) {
    asm volatile("ldmatrix.sync.aligned.m8n8.x4.trans.shared.b16 {%0,%1,%2,%3},[%4];"
        : "=r"(r[0]), "=r"(r[1]), "=r"(r[2]), "=r"(r[3]) : "r"(addr));
}
__device__ __forceinline__ void mma16816(float* c, const unsigned* a, const unsigned* b) {
    asm volatile("mma.sync.aligned.m16n8k16.row.col.f32.bf16.bf16.f32 "
        "{%0,%1,%2,%3},{%4,%5,%6,%7},{%8,%9},{%0,%1,%2,%3};"
        : "+f"(c[0]), "+f"(c[1]), "+f"(c[2]), "+f"(c[3])
        : "r"(a[0]), "r"(a[1]), "r"(a[2]), "r"(a[3]), "r"(b[0]), "r"(b[1]));
}
__device__ __forceinline__ void cp_async16(unsigned saddr, const void* g) {
    asm volatile("cp.async.cg.shared.global [%0], [%1], 16;" :: "r"(saddr), "l"(g));
}

template<int EPI>
__global__ void __launch_bounds__(256) gemm3_kernel(
    const bf16* __restrict__ Ahi, const bf16* __restrict__ Alo,
    const bf16* __restrict__ Bhi, const bf16* __restrict__ Blo,
    const float* __restrict__ bias, const float* __restrict__ res,
    float* __restrict__ Cf, bf16* __restrict__ Chi, bf16* __restrict__ Clo,
    int M, int N, int K)
{
    extern __shared__ __align__(16) bf16 smem[];
    bf16* sA = smem;               // [buf][p][128][ASTRIDE]
    bf16* sB = smem + SA_ELEMS;    // [buf][p][32][BSTRIDE]
    const int tid = threadIdx.x;
    const int lane = tid & 31, wid = tid >> 5;
    const int wm = wid & 3, wn = wid >> 2;
    const int bm = blockIdx.y * GBM, bn = blockIdx.x * GBN;

    unsigned sA_base = (unsigned)__cvta_generic_to_shared(sA);
    unsigned sB_base = (unsigned)__cvta_generic_to_shared(sB);

    float acc[2][8][4] = {};

    auto issue = [&](int it, int buf) {
        int k0 = it * GBK;
        #pragma unroll
        for (int j = 0; j < 4; j++) {           // A: 1024 16B chunks total
            int c = tid + j * 256;
            int p = c >> 9, rem = c & 511;
            int r = rem >> 2, kc = (rem & 3) << 3;
            const bf16* src = (p ? Alo : Ahi) + (size_t)(bm + r) * K + k0 + kc;
            unsigned dst = sA_base + (unsigned)((((p ? 2 : 0) + buf) == 0 ? 0 : 0, ((buf*2 + p)*GBM + r)*ASTRIDE + kc)) * 2u;
            cp_async16(dst, src);
        }
        #pragma unroll
        for (int j = 0; j < 4; j++) {           // B: 1024 16B chunks total
            int c = tid + j * 256;
            int p = c >> 9, rem = c & 511;
            int k = rem >> 4, nc = (rem & 15) << 3;
            const bf16* src = (p ? Blo : Bhi) + (size_t)(k0 + k) * N + bn + nc;
            unsigned dst = sB_base + (unsigned)(((buf*2 + p)*GBK + k)*BSTRIDE + nc) * 2u;
            cp_async16(dst, src);
        }
        asm volatile("cp.async.commit_group;" ::: "memory");
    };

    issue(0, 0);
    const int NIT = K >> 5;
    for (int it = 0; it < NIT; it++) {
        int buf = it & 1;
        if (it + 1 < NIT) {
            issue(it + 1, buf ^ 1);
            asm volatile("cp.async.wait_group 1;" ::: "memory");
        } else {
            asm volatile("cp.async.wait_group 0;" ::: "memory");
        }
        __syncthreads();
        #pragma unroll
        for (int ks = 0; ks < 2; ks++) {
            unsigned afrag[2][2][4];
            unsigned bfrag[2][8][2];
            int arow = wm * 32 + (lane & 15);
            int acol = ks * 16 + ((lane >> 4) << 3);
            #pragma unroll
            for (int mt = 0; mt < 2; mt++)
                #pragma unroll
                for (int p = 0; p < 2; p++)
                    ldsm4(afrag[mt][p],
                          sA_base + (unsigned)(((buf*2 + p)*GBM + arow + mt*16)*ASTRIDE + acol) * 2u);
            int brow = ks * 16 + (lane & 15);
            #pragma unroll
            for (int ng = 0; ng < 4; ng++) {
                int bcol = wn * 64 + ng * 16 + ((lane >> 4) << 3);
                #pragma unroll
                for (int p = 0; p < 2; p++) {
                    unsigned r4[4];
                    ldsm4t(r4, sB_base + (unsigned)(((buf*2 + p)*GBK + brow)*BSTRIDE + bcol) * 2u);
                    bfrag[p][2*ng][0]   = r4[0]; bfrag[p][2*ng][1]   = r4[1];
                    bfrag[p][2*ng+1][0] = r4[2]; bfrag[p][2*ng+1][1] = r4[3];
                }
            }
            #pragma unroll
            for (int mt = 0; mt < 2; mt++)
                #pragma unroll
                for (int nt = 0; nt < 8; nt++) {
                    mma16816(acc[mt][nt], afrag[mt][0], bfrag[0][nt]);   // hi*hi
                    mma16816(acc[mt][nt], afrag[mt][0], bfrag[1][nt]);   // hi*lo
                    mma16816(acc[mt][nt], afrag[mt][1], bfrag[0][nt]);   // lo*hi
                }
        }
        __syncthreads();
    }

    // epilogue
    #pragma unroll
    for (int mt = 0; mt < 2; mt++) {
        #pragma unroll
        for (int nt = 0; nt < 8; nt++) {
            int r0 = bm + wm * 32 + mt * 16 + (lane >> 2);
            int c0 = bn + wn * 64 + nt * 8 + ((lane & 3) << 1);
            #pragma unroll
            for (int hh = 0; hh < 2; hh++) {
                int rr = r0 + hh * 8;
                #pragma unroll
                for (int cc = 0; cc < 2; cc++) {
                    int col = c0 + cc;
                    float v = acc[mt][nt][hh*2 + cc] + bias[col];
                    size_t idx = (size_t)rr * N + col;
                    if (EPI == 0) {
                        Cf[idx] = v;
                    } else if (EPI == 1) {
                        Cf[idx] = res[idx] + v;
                    } else {
                        v = fmaxf(v, 0.f);
                        bf16 vh, vl; split2(v, vh, vl);
                        Chi[idx] = vh; Clo[idx] = vl;
                    }
                }
            }
        }
    }
}

// ---------------- fused causal attention (flash-lite) ------------------------
#define BQ 32
#define BKT 32
__global__ __launch_bounds__(256) void attn_kernel(
    const float* __restrict__ qkv, const float* __restrict__ amask,
    bf16* __restrict__ ctxhi, bf16* __restrict__ ctxlo)
{
    __shared__ __align__(16) float Qs[BQ][HD];
    __shared__ __align__(16) float Ks[BKT][HD];
    __shared__ __align__(16) float Vs[BKT][HD];
    __shared__ float Ss[BQ][BKT];
    __shared__ float mrow[BQ], lrow[BQ], crow[BQ];

    int tid = threadIdx.x;
    int bh = blockIdx.y;
    int b = bh / Hc, hh = bh % Hc;
    int q0 = blockIdx.x * BQ;

    const float* qbase = qkv + (size_t)b * Tc * 3 * Dc + hh * HD;
    const float* kbase = qbase + Dc;
    const float* vbase = qbase + 2 * Dc;

    for (int i = tid; i < BQ * HD; i += 256) {
        int r = i >> 6, d = i & 63;
        Qs[r][d] = qbase[(size_t)(q0 + r) * 3 * Dc + d];
    }
    if (tid < BQ) { mrow[tid] = -1e30f; lrow[tid] = 0.f; }

    int tq = tid >> 3;
    int dbase = (tid & 7) << 3;
    float acc[8] = {};
    const float scale = 0.125f;

    int ntiles = blockIdx.x + 1;
    for (int kt = 0; kt < ntiles; kt++) {
        int kk0 = kt * BKT;
        __syncthreads();
        for (int i = tid; i < BKT * HD; i += 256) {
            int r = i >> 6, d = i & 63;
            Ks[r][d] = kbase[(size_t)(kk0 + r) * 3 * Dc + d];
            Vs[r][d] = vbase[(size_t)(kk0 + r) * 3 * Dc + d];
        }
        __syncthreads();
        {
            int sq = tid >> 3;
            int c0 = (tid & 7) << 2;
            float sv[4] = {0.f, 0.f, 0.f, 0.f};
            #pragma unroll
            for (int d = 0; d < HD; d++) {
                float qv = Qs[sq][d];
                sv[0] += qv * Ks[c0 + 0][d];
                sv[1] += qv * Ks[c0 + 1][d];
                sv[2] += qv * Ks[c0 + 2][d];
                sv[3] += qv * Ks[c0 + 3][d];
            }
            int qg = q0 + sq;
            #pragma unroll
            for (int j = 0; j < 4; j++) {
                int kg = kk0 + c0 + j;
                float s;
                if (kg <= qg)
                    s = sv[j] * scale + (1.0f - amask[b * Tc + kg]) * MASK_BIAS;
                else
                    s = -1e30f;
                Ss[sq][c0 + j] = s;
            }
        }
        __syncthreads();
        if (tid < BQ) {
            float m = mrow[tid];
            float tm = m;
            #pragma unroll
            for (int j = 0; j < BKT; j++) tm = fmaxf(tm, Ss[tid][j]);
            float corr = __expf(m - tm);
            float l = lrow[tid] * corr;
            #pragma unroll
            for (int j = 0; j < BKT; j++) {
                float p = __expf(Ss[tid][j] - tm);
                Ss[tid][j] = p;
                l += p;
            }
            mrow[tid] = tm; lrow[tid] = l; crow[tid] = corr;
        }
        __syncthreads();
        float corr = crow[tq];
        #pragma unroll
        for (int j = 0; j < 8; j++) acc[j] *= corr;
        #pragma unroll 4
        for (int kkk = 0; kkk < BKT; kkk++) {
            float p = Ss[tq][kkk];
            float4 v0 = *(const float4*)&Vs[kkk][dbase];
            float4 v1 = *(const float4*)&Vs[kkk][dbase + 4];
            acc[0] += p * v0.x; acc[1] += p * v0.y;
            acc[2] += p * v0.z; acc[3] += p * v0.w;
            acc[4] += p * v1.x; acc[5] += p * v1.y;
            acc[6] += p * v1.z; acc[7] += p * v1.w;
        }
    }
    __syncthreads();
    float linv = 1.0f / lrow[tq];
    size_t obase = ((size_t)(b * Tc + q0 + tq)) * Dc + hh * HD + dbase;
    #pragma unroll
    for (int j = 0; j < 8; j++) {
        float v = acc[j] * linv;
        bf16 vh, vl; split2(v, vh, vl);
        ctxhi[obase + j] = vh;
        ctxlo[obase + j] = vl;
    }
}

// ---------------- launch -----------------------------------------------------
extern "C" void kernel_launch(void* const* d_in, const int* in_sizes, int n_in,
                              void* d_out, int out_size)
{
    const float* emb    = (const float*)d_in[0];
    const float* amask  = (const float*)d_in[1];
    const float* ln1_w  = (const float*)d_in[2];
    const float* ln1_b  = (const float*)d_in[3];
    const float* attn_w = (const float*)d_in[4];
    const float* attn_b = (const float*)d_in[5];
    const float* proj_w = (const float*)d_in[6];
    const float* proj_b = (const float*)d_in[7];
    const float* ln2_w  = (const float*)d_in[8];
    const float* ln2_b  = (const float*)d_in[9];
    const float* fc_w   = (const float*)d_in[10];
    const float* fc_b   = (const float*)d_in[11];
    const float* fcp_w  = (const float*)d_in[12];
    const float* fcp_b  = (const float*)d_in[13];
    const float* lnf_w  = (const float*)d_in[14];
    const float* lnf_b  = (const float*)d_in[15];
    float* out = (float*)d_out;

    float *h, *qkvb;
    bf16 *xhi, *xlo, *chi, *clo, *ahi, *alo;
    bf16 *wq_h, *wq_l, *wp_h, *wp_l, *wf_h, *wf_l, *wg_h, *wg_l;
    cudaGetSymbolAddress((void**)&h,    g_h);
    cudaGetSymbolAddress((void**)&qkvb, g_qkv);
    cudaGetSymbolAddress((void**)&xhi,  g_xhi);  cudaGetSymbolAddress((void**)&xlo, g_xlo);
    cudaGetSymbolAddress((void**)&chi,  g_chi);  cudaGetSymbolAddress((void**)&clo, g_clo);
    cudaGetSymbolAddress((void**)&ahi,  g_ahi);  cudaGetSymbolAddress((void**)&alo, g_alo);
    cudaGetSymbolAddress((void**)&wq_h, g_wqkv_hi); cudaGetSymbolAddress((void**)&wq_l, g_wqkv_lo);
    cudaGetSymbolAddress((void**)&wp_h, g_wprj_hi); cudaGetSymbolAddress((void**)&wp_l, g_wprj_lo);
    cudaGetSymbolAddress((void**)&wf_h, g_wfc_hi);  cudaGetSymbolAddress((void**)&wf_l, g_wfc_lo);
    cudaGetSymbolAddress((void**)&wg_h, g_wfp_hi);  cudaGetSymbolAddress((void**)&wg_l, g_wfp_lo);

    // raise dynamic smem limit for GEMMs (idempotent, cheap)
    cudaFuncSetAttribute(gemm3_kernel<0>, cudaFuncAttributeMaxDynamicSharedMemorySize, GSMEM_BYTES);
    cudaFuncSetAttribute(gemm3_kernel<1>, cudaFuncAttributeMaxDynamicSharedMemorySize, GSMEM_BYTES);
    cudaFuncSetAttribute(gemm3_kernel<2>, cudaFuncAttributeMaxDynamicSharedMemorySize, GSMEM_BYTES);

    // weight splits (run per replay; ~0.1 ms HBM-bound)
    { int n4 = Lc*Dc*3*Dc/4; split4_kernel<<<(n4+255)/256, 256>>>(attn_w, wq_h, wq_l, n4); }
    { int n4 = Lc*Dc*Dc/4;   split4_kernel<<<(n4+255)/256, 256>>>(proj_w, wp_h, wp_l, n4); }
    { int n4 = Lc*Dc*Ic/4;   split4_kernel<<<(n4+255)/256, 256>>>(fc_w,   wf_h, wf_l, n4); }
    { int n4 = Lc*Ic*Dc/4;   split4_kernel<<<(n4+255)/256, 256>>>(fcp_w,  wg_h, wg_l, n4); }

    // h = inputs_embeds
    { int n = ROWS * Dc; copy_kernel<<<(n + 255) / 256, 256>>>(emb, h, n); }

    for (int l = 0; l < Lc; l++) {
        // x = ln1(h) -> split
        ln_kernel<true><<<ROWS, 256>>>(h, ln1_w + (size_t)l*Dc, ln1_b + (size_t)l*Dc,
                                       nullptr, xhi, xlo);
        // qkv = x @ attn_w + attn_b  (fp32 out)
        gemm3_kernel<0><<<dim3(3*Dc/GBN, ROWS/GBM), 256, GSMEM_BYTES>>>(
            xhi, xlo, wq_h + (size_t)l*Dc*3*Dc, wq_l + (size_t)l*Dc*3*Dc,
            attn_b + (size_t)l*3*Dc, nullptr, qkvb, nullptr, nullptr,
            ROWS, 3*Dc, Dc);
        // ctx = attention(qkv) -> split
        attn_kernel<<<dim3(Tc/BQ, Bc*Hc), 256>>>(qkvb, amask, chi, clo);
        // h = h + ctx @ proj_w + proj_b
        gemm3_kernel<1><<<dim3(Dc/GBN, ROWS/GBM), 256, GSMEM_BYTES>>>(
            chi, clo, wp_h + (size_t)l*Dc*Dc, wp_l + (size_t)l*Dc*Dc,
            proj_b + (size_t)l*Dc, h, h, nullptr, nullptr,
            ROWS, Dc, Dc);
        // x = ln2(h) -> split
        ln_kernel<true><<<ROWS, 256>>>(h, ln2_w + (size_t)l*Dc, ln2_b + (size_t)l*Dc,
                                       nullptr, xhi, xlo);
        // act = relu(x @ fc_w + fc_b) -> split
        gemm3_kernel<2><<<dim3(Ic/GBN, ROWS/GBM), 256, GSMEM_BYTES>>>(
            xhi, xlo, wf_h + (size_t)l*Dc*Ic, wf_l + (size_t)l*Dc*Ic,
            fc_b + (size_t)l*Ic, nullptr, nullptr, ahi, alo,
            ROWS, Ic, Dc);
        // h = h + act @ fcp_w + fcp_b
        gemm3_kernel<1><<<dim3(Dc/GBN, ROWS/GBM), 256, GSMEM_BYTES>>>(
            ahi, alo, wg_h + (size_t)l*Ic*Dc, wg_l + (size_t)l*Ic*Dc,
            fcp_b + (size_t)l*Dc, h, h, nullptr, nullptr,
            ROWS, Dc, Ic);
    }
    // out = ln_f(h) (fp32)
    ln_kernel<false><<<ROWS, 256>>>(h, lnf_w, lnf_b, out, nullptr, nullptr);
}